// round 7
// baseline (speedup 1.0000x reference)
#include <cuda_runtime.h>
#include <cuda_fp16.h>
#include <stdint.h>

#define HASH_MASK ((1u << 19) - 1u)
#define RES 128.0f
#define P1 2654435761u
#define P2 805459861u

#define QDIM 128
// yz-quad fp16 grid: entry(ix, fy, fz) = packed half2 of
// {v(y,z), v(y,z+1), v(y+1,z), v(y+1,z+1)}; 16 B per entry; 33.8 MB
__device__ uint4 g_quad[129 * QDIM * QDIM];

__device__ __forceinline__ float2 up2(uint32_t u) {
    __half2 h = *reinterpret_cast<__half2*>(&u);
    return __half22float2(h);
}

// ---------------- Pass 1: densify (XOR-window coalesced gathers) ----------------
// Block per 8x8 (y,z) tile, covering ALL ix in [0,128].
// Key: hash = ix ^ y*P1 ^ z*P2 — for fixed (y,z), 32 consecutive ix read one
// aligned 32-entry (256B) window of the table: 8 wavefronts/warp, not 32.
#define TY 8
#define TZ 8
#define SROW 133   // padded row stride (words) to dodge smem bank conflicts

__global__ void __launch_bounds__(256) densify_kernel(const float2* __restrict__ ht)
{
    int by = (blockIdx.x >> 4) * TY;   // y0: 0,8,...,120
    int bz = (blockIdx.x & 15) * TZ;   // z0: 0,8,...,120

    __shared__ uint32_t s[(TY + 1) * (TZ + 1) * SROW];  // 81 rows x 133 words

    int tid = threadIdx.x;
    int warp = tid >> 5;
    int lane = tid & 31;

    // Load phase: row r = yl*9+zl, lanes sweep ix (coalesced XOR windows).
    for (int r = warp; r < (TY + 1) * (TZ + 1); r += 8) {
        int yl = r / (TZ + 1);
        int zl = r - yl * (TZ + 1);
        uint32_t base = ((uint32_t)(by + yl) * P1) ^ ((uint32_t)(bz + zl) * P2);
        for (int ix = lane; ix < 129; ix += 32) {
            float2 v = __ldg(&ht[(base ^ (uint32_t)ix) & HASH_MASK]);
            __half2 hh = __floats2half2_rn(v.x, v.y);
            s[r * SROW + ix] = *reinterpret_cast<uint32_t*>(&hh);
        }
    }
    __syncthreads();

    // Store phase: quad entries, lanes vary (yl,zl) for z-coalesced STG.128.
    for (int e = tid; e < 129 * TY * TZ; e += 256) {
        int ix = e >> 6;           // e / 64
        int q  = e & 63;
        int yl = q >> 3;
        int zl = q & 7;
        int r = yl * (TZ + 1) + zl;
        uint32_t w0 = s[r * SROW + ix];              // (y,  z)
        uint32_t w1 = s[(r + 1) * SROW + ix];        // (y,  z+1)
        uint32_t w2 = s[(r + TZ + 1) * SROW + ix];   // (y+1,z)
        uint32_t w3 = s[(r + TZ + 2) * SROW + ix];   // (y+1,z+1)
        g_quad[(ix * QDIM + by + yl) * QDIM + (bz + zl)] =
            make_uint4(w0, w1, w2, w3);
    }
}

// ---------------- Pass 2: trilinear interp, 4 points/thread ----------------
__device__ __forceinline__ void interp_one(
    float sx, float sy, float sz, float& oa, float& ob)
{
    float fxf = floorf(sx), fyf = floorf(sy), fzf = floorf(sz);
    int fx = (int)fxf, fy = (int)fyf, fz = (int)fzf;
    float dx = sx - fxf, dy = sy - fyf, dz = sz - fzf;
    // ceil-corner vs floor+1 differ only at integral coords where the lerp
    // weight is exactly 0 -> bit-equivalent.

    int base = (fx * QDIM + fy) * QDIM + fz;
    uint4 q0 = __ldg(&g_quad[base]);               // x = fx
    uint4 q1 = __ldg(&g_quad[base + QDIM * QDIM]); // x = fx+1

    float2 v000 = up2(q0.x), v001 = up2(q0.y), v010 = up2(q0.z), v011 = up2(q0.w);
    float2 v100 = up2(q1.x), v101 = up2(q1.y), v110 = up2(q1.z), v111 = up2(q1.w);

    float omx = 1.0f - dx, omy = 1.0f - dy, omz = 1.0f - dz;

    float c00a = v000.x * omx + v100.x * dx;
    float c00b = v000.y * omx + v100.y * dx;
    float c01a = v001.x * omx + v101.x * dx;
    float c01b = v001.y * omx + v101.y * dx;
    float c10a = v010.x * omx + v110.x * dx;
    float c10b = v010.y * omx + v110.y * dx;
    float c11a = v011.x * omx + v111.x * dx;
    float c11b = v011.y * omx + v111.y * dx;

    float c0a = c00a * omy + c10a * dy;
    float c0b = c00b * omy + c10b * dy;
    float c1a = c01a * omy + c11a * dy;
    float c1b = c01b * omy + c11b * dy;

    oa = c0a * omz + c1a * dz;
    ob = c0b * omz + c1b * dz;
}

__global__ void __launch_bounds__(256) ngp_interp_kernel(
    const float* __restrict__ x,
    float2* __restrict__ out,
    int n)
{
    int t = blockIdx.x * blockDim.x + threadIdx.x;
    int i0 = t * 4;
    if (i0 >= n) return;

    if (i0 + 3 < n) {
        // Vectorized: 3x LDG.128 covers 4 points (12 floats), streaming.
        const float4* __restrict__ x4 = (const float4*)x;
        float4 a = __ldcs(&x4[3 * t + 0]);
        float4 b = __ldcs(&x4[3 * t + 1]);
        float4 c = __ldcs(&x4[3 * t + 2]);

        float o0a, o0b, o1a, o1b, o2a, o2b, o3a, o3b;
        interp_one(a.x * RES, a.y * RES, a.z * RES, o0a, o0b);
        interp_one(a.w * RES, b.x * RES, b.y * RES, o1a, o1b);
        interp_one(b.z * RES, b.w * RES, c.x * RES, o2a, o2b);
        interp_one(c.y * RES, c.z * RES, c.w * RES, o3a, o3b);

        float4* __restrict__ out4 = (float4*)out;
        __stcs(&out4[2 * t + 0], make_float4(o0a, o0b, o1a, o1b));
        __stcs(&out4[2 * t + 1], make_float4(o2a, o2b, o3a, o3b));
    } else {
        for (int i = i0; i < n; i++) {
            float sx = __ldcs(&x[3 * i + 0]) * RES;
            float sy = __ldcs(&x[3 * i + 1]) * RES;
            float sz = __ldcs(&x[3 * i + 2]) * RES;
            float oa, ob;
            interp_one(sx, sy, sz, oa, ob);
            __stcs(&out[i], make_float2(oa, ob));
        }
    }
}

extern "C" void kernel_launch(void* const* d_in, const int* in_sizes, int n_in,
                              void* d_out, int out_size) {
    const float* x = (const float*)d_in[0];
    const float2* ht = (const float2*)d_in[1];
    float2* out = (float2*)d_out;
    int n = in_sizes[0] / 3;

    densify_kernel<<<256, 256>>>(ht);

    int threads = 256;
    int pts_per_block = threads * 4;
    int blocks = (n + pts_per_block - 1) / pts_per_block;
    ngp_interp_kernel<<<blocks, threads>>>(x, out, n);
}

// round 8
// speedup vs baseline: 1.1945x; 1.1945x over previous
#include <cuda_runtime.h>
#include <cuda_fp16.h>
#include <stdint.h>

#define HASH_MASK ((1u << 19) - 1u)
#define RES 128.0f
#define P1 2654435761u
#define P2 805459861u

#define QDIM 128
#define XSTRIDE (QDIM * QDIM)
// yz-quad fp16 grid: entry(ix, fy, fz) = packed half2 of
// {v(y,z), v(y,z+1), v(y+1,z), v(y+1,z+1)}; 16 B per entry; 33.8 MB
__device__ uint4 g_quad[129 * QDIM * QDIM];

__device__ __forceinline__ float2 up2(uint32_t u) {
    __half2 h = *reinterpret_cast<__half2*>(&u);
    return __half22float2(h);
}

// ---------------- Pass 1: densify (XOR-window coalesced gathers) ----------------
// Block per 4x8 (y,z) tile covering all ix in [0,128]. For fixed (y,z),
// 32 consecutive ix read one aligned 32-entry window of the table (XOR-linear
// hash in ix) -> coalesced-ish gathers instead of 32-way scatter.
#define TY 4
#define TZ 8
#define NROWS ((TY + 1) * (TZ + 1))   // 45
#define SROW 133                      // padded stride to dodge bank conflicts

__global__ void __launch_bounds__(256) densify_kernel(const float2* __restrict__ ht)
{
    int by = (blockIdx.x >> 4) * TY;   // 32 y-tiles
    int bz = (blockIdx.x & 15) * TZ;   // 16 z-tiles

    __shared__ uint32_t s[NROWS * SROW];

    int tid = threadIdx.x;
    int warp = tid >> 5;
    int lane = tid & 31;

    for (int r = warp; r < NROWS; r += 8) {
        int yl = r / (TZ + 1);
        int zl = r - yl * (TZ + 1);
        uint32_t base = ((uint32_t)(by + yl) * P1) ^ ((uint32_t)(bz + zl) * P2);
        for (int ix = lane; ix < 129; ix += 32) {
            float2 v = __ldg(&ht[(base ^ (uint32_t)ix) & HASH_MASK]);
            __half2 hh = __floats2half2_rn(v.x, v.y);
            s[r * SROW + ix] = *reinterpret_cast<uint32_t*>(&hh);
        }
    }
    __syncthreads();

    // Store phase: lanes sweep (yl,zl) -> 4 x 128B coalesced STG.128 segments.
    for (int e = tid; e < 129 * TY * TZ; e += 256) {
        int ix = e >> 5;
        int q  = e & 31;
        int yl = q >> 3;
        int zl = q & 7;
        int r = yl * (TZ + 1) + zl;
        uint32_t w0 = s[r * SROW + ix];              // (y,  z)
        uint32_t w1 = s[(r + 1) * SROW + ix];        // (y,  z+1)
        uint32_t w2 = s[(r + TZ + 1) * SROW + ix];   // (y+1,z)
        uint32_t w3 = s[(r + TZ + 2) * SROW + ix];   // (y+1,z+1)
        g_quad[(ix * QDIM + by + yl) * QDIM + (bz + zl)] =
            make_uint4(w0, w1, w2, w3);
    }
}

// ---------------- Pass 2: trilinear interp, 2 points/thread ----------------
__device__ __forceinline__ void lerp8(
    uint4 q0, uint4 q1, float dx, float dy, float dz, float& oa, float& ob)
{
    float2 v000 = up2(q0.x), v001 = up2(q0.y), v010 = up2(q0.z), v011 = up2(q0.w);
    float2 v100 = up2(q1.x), v101 = up2(q1.y), v110 = up2(q1.z), v111 = up2(q1.w);

    float omx = 1.0f - dx, omy = 1.0f - dy, omz = 1.0f - dz;

    float c00a = v000.x * omx + v100.x * dx;
    float c00b = v000.y * omx + v100.y * dx;
    float c01a = v001.x * omx + v101.x * dx;
    float c01b = v001.y * omx + v101.y * dx;
    float c10a = v010.x * omx + v110.x * dx;
    float c10b = v010.y * omx + v110.y * dx;
    float c11a = v011.x * omx + v111.x * dx;
    float c11b = v011.y * omx + v111.y * dx;

    float c0a = c00a * omy + c10a * dy;
    float c0b = c00b * omy + c10b * dy;
    float c1a = c01a * omy + c11a * dy;
    float c1b = c01b * omy + c11b * dy;

    oa = c0a * omz + c1a * dz;
    ob = c0b * omz + c1b * dz;
}

__global__ void __launch_bounds__(256) ngp_interp_kernel(
    const float* __restrict__ x,
    float2* __restrict__ out,
    int n)
{
    int t = blockIdx.x * blockDim.x + threadIdx.x;
    int i0 = t * 2;
    if (i0 >= n) return;

    // 3x aligned LDG.64 per thread covers both points (6 floats), streaming.
    const float2* __restrict__ x2 = (const float2*)x;
    float2 a = __ldcs(&x2[3 * t + 0]);
    float2 b = __ldcs(&x2[3 * t + 1]);
    float2 c = __ldcs(&x2[3 * t + 2]);

    // Point 0
    float sx0 = a.x * RES, sy0 = a.y * RES, sz0 = b.x * RES;
    float fx0 = floorf(sx0), fy0 = floorf(sy0), fz0 = floorf(sz0);
    int b0 = ((int)fx0 * QDIM + (int)fy0) * QDIM + (int)fz0;
    // Point 1
    float sx1 = b.y * RES, sy1 = c.x * RES, sz1 = c.y * RES;
    float fx1 = floorf(sx1), fy1 = floorf(sy1), fz1 = floorf(sz1);
    int b1 = ((int)fx1 * QDIM + (int)fy1) * QDIM + (int)fz1;

    // All 4 gathers in flight before any math (MLP=4 per thread).
    uint4 p00 = __ldg(&g_quad[b0]);
    uint4 p01 = __ldg(&g_quad[b0 + XSTRIDE]);
    uint4 p10 = __ldg(&g_quad[b1]);
    uint4 p11 = __ldg(&g_quad[b1 + XSTRIDE]);

    float o0a, o0b, o1a, o1b;
    lerp8(p00, p01, sx0 - fx0, sy0 - fy0, sz0 - fz0, o0a, o0b);
    lerp8(p10, p11, sx1 - fx1, sy1 - fy1, sz1 - fz1, o1a, o1b);

    if (i0 + 1 < n) {
        float4* __restrict__ out4 = (float4*)out;
        __stcs(&out4[t], make_float4(o0a, o0b, o1a, o1b));
    } else {
        __stcs(&out[i0], make_float2(o0a, o0b));
    }
}

extern "C" void kernel_launch(void* const* d_in, const int* in_sizes, int n_in,
                              void* d_out, int out_size) {
    const float* x = (const float*)d_in[0];
    const float2* ht = (const float2*)d_in[1];
    float2* out = (float2*)d_out;
    int n = in_sizes[0] / 3;

    densify_kernel<<<512, 256>>>(ht);

    int threads = 256;
    int pts_per_block = threads * 2;
    int blocks = (n + pts_per_block - 1) / pts_per_block;
    ngp_interp_kernel<<<blocks, threads>>>(x, out, n);
}

// round 9
// speedup vs baseline: 1.2422x; 1.0400x over previous
#include <cuda_runtime.h>
#include <cuda_fp16.h>
#include <stdint.h>

#define HASH_MASK ((1u << 19) - 1u)
#define RES 128.0f
#define P1 2654435761u
#define P2 805459861u

#define GD 128
// octo fp16 grid: entry(fx,fy,fz) = 8 packed half2 words:
// [ quad(fx):  v(y,z), v(y,z+1), v(y+1,z), v(y+1,z+1),
//   quad(fx+1): same four ]
// 32 B per entry, 32B-aligned -> exactly one L2 sector per point. 67 MB.
__device__ __align__(32) uint32_t g_octo[GD * GD * GD * 8];

__device__ __forceinline__ float2 up2(uint32_t u) {
    __half2 h = *reinterpret_cast<__half2*>(&u);
    return __half22float2(h);
}

// Blackwell 256-bit global load: one instruction, one 32B sector per lane.
__device__ __forceinline__ void ld_octo(const uint32_t* p, uint32_t r[8]) {
    asm("ld.global.v8.b32 {%0,%1,%2,%3,%4,%5,%6,%7}, [%8];"
        : "=r"(r[0]), "=r"(r[1]), "=r"(r[2]), "=r"(r[3]),
          "=r"(r[4]), "=r"(r[5]), "=r"(r[6]), "=r"(r[7])
        : "l"(p));
}

__device__ __forceinline__ void st_octo(uint32_t* p, uint32_t w0, uint32_t w1,
                                        uint32_t w2, uint32_t w3, uint32_t w4,
                                        uint32_t w5, uint32_t w6, uint32_t w7) {
    asm volatile("st.global.v8.b32 [%0], {%1,%2,%3,%4,%5,%6,%7,%8};"
                 :: "l"(p), "r"(w0), "r"(w1), "r"(w2), "r"(w3),
                    "r"(w4), "r"(w5), "r"(w6), "r"(w7) : "memory");
}

// ---------------- Pass 1: densify (XOR-window coalesced gathers) ----------------
// Block per 4x8 (y,z) tile covering all ix in [0,128]. For fixed (y,z),
// consecutive ix read one aligned 32-entry window of the table (hash is
// XOR-linear in ix).
#define TY 4
#define TZ 8
#define NROWS ((TY + 1) * (TZ + 1))   // 45
#define SROW 133                      // padded stride vs bank conflicts

__global__ void __launch_bounds__(256) densify_kernel(const float2* __restrict__ ht)
{
    int by = (blockIdx.x >> 4) * TY;   // 32 y-tiles
    int bz = (blockIdx.x & 15) * TZ;   // 16 z-tiles

    __shared__ uint32_t s[NROWS * SROW];

    int tid = threadIdx.x;
    int warp = tid >> 5;
    int lane = tid & 31;

    for (int r = warp; r < NROWS; r += 8) {
        int yl = r / (TZ + 1);
        int zl = r - yl * (TZ + 1);
        uint32_t base = ((uint32_t)(by + yl) * P1) ^ ((uint32_t)(bz + zl) * P2);
        for (int ix = lane; ix < 129; ix += 32) {
            float2 v = __ldg(&ht[(base ^ (uint32_t)ix) & HASH_MASK]);
            __half2 hh = __floats2half2_rn(v.x, v.y);
            s[r * SROW + ix] = *reinterpret_cast<uint32_t*>(&hh);
        }
    }
    __syncthreads();

    // Store phase: 32B octo entries; lanes sweep (yl,zl) -> contiguous sectors.
    for (int e = tid; e < GD * TY * TZ; e += 256) {
        int ix = e >> 5;
        int q  = e & 31;
        int yl = q >> 3;
        int zl = q & 7;
        int r = yl * (TZ + 1) + zl;
        uint32_t w0 = s[r * SROW + ix];               // x0: (y,  z)
        uint32_t w1 = s[(r + 1) * SROW + ix];         // x0: (y,  z+1)
        uint32_t w2 = s[(r + TZ + 1) * SROW + ix];    // x0: (y+1,z)
        uint32_t w3 = s[(r + TZ + 2) * SROW + ix];    // x0: (y+1,z+1)
        uint32_t w4 = s[r * SROW + ix + 1];           // x1: (y,  z)
        uint32_t w5 = s[(r + 1) * SROW + ix + 1];
        uint32_t w6 = s[(r + TZ + 1) * SROW + ix + 1];
        uint32_t w7 = s[(r + TZ + 2) * SROW + ix + 1];
        uint32_t* dst = &g_octo[(((ix * GD) + by + yl) * GD + bz + zl) * 8];
        st_octo(dst, w0, w1, w2, w3, w4, w5, w6, w7);
    }
}

// ---------------- Pass 2: trilinear interp, 2 points/thread, 1 LDG.256/pt ----------------
__device__ __forceinline__ void lerp8(
    const uint32_t w[8], float dx, float dy, float dz, float& oa, float& ob)
{
    float2 v000 = up2(w[0]), v001 = up2(w[1]), v010 = up2(w[2]), v011 = up2(w[3]);
    float2 v100 = up2(w[4]), v101 = up2(w[5]), v110 = up2(w[6]), v111 = up2(w[7]);

    float omx = 1.0f - dx, omy = 1.0f - dy, omz = 1.0f - dz;

    float c00a = v000.x * omx + v100.x * dx;
    float c00b = v000.y * omx + v100.y * dx;
    float c01a = v001.x * omx + v101.x * dx;
    float c01b = v001.y * omx + v101.y * dx;
    float c10a = v010.x * omx + v110.x * dx;
    float c10b = v010.y * omx + v110.y * dx;
    float c11a = v011.x * omx + v111.x * dx;
    float c11b = v011.y * omx + v111.y * dx;

    float c0a = c00a * omy + c10a * dy;
    float c0b = c00b * omy + c10b * dy;
    float c1a = c01a * omy + c11a * dy;
    float c1b = c01b * omy + c11b * dy;

    oa = c0a * omz + c1a * dz;
    ob = c0b * omz + c1b * dz;
}

__global__ void __launch_bounds__(256) ngp_interp_kernel(
    const float* __restrict__ x,
    float2* __restrict__ out,
    int n)
{
    int t = blockIdx.x * blockDim.x + threadIdx.x;
    int i0 = t * 2;
    if (i0 >= n) return;

    // 3x aligned LDG.64 covers both points (6 floats), streaming.
    const float2* __restrict__ x2 = (const float2*)x;
    float2 a = __ldcs(&x2[3 * t + 0]);
    float2 b = __ldcs(&x2[3 * t + 1]);
    float2 c = __ldcs(&x2[3 * t + 2]);

    float sx0 = a.x * RES, sy0 = a.y * RES, sz0 = b.x * RES;
    float fx0 = floorf(sx0), fy0 = floorf(sy0), fz0 = floorf(sz0);
    int b0 = ((int)fx0 * GD + (int)fy0) * GD + (int)fz0;

    float sx1 = b.y * RES, sy1 = c.x * RES, sz1 = c.y * RES;
    float fx1 = floorf(sx1), fy1 = floorf(sy1), fz1 = floorf(sz1);
    int b1 = ((int)fx1 * GD + (int)fy1) * GD + (int)fz1;

    // Two 256-bit gathers in flight before any math.
    uint32_t w0[8], w1[8];
    ld_octo(&g_octo[b0 * 8], w0);
    ld_octo(&g_octo[b1 * 8], w1);

    float o0a, o0b, o1a, o1b;
    lerp8(w0, sx0 - fx0, sy0 - fy0, sz0 - fz0, o0a, o0b);
    lerp8(w1, sx1 - fx1, sy1 - fy1, sz1 - fz1, o1a, o1b);

    if (i0 + 1 < n) {
        float4* __restrict__ out4 = (float4*)out;
        __stcs(&out4[t], make_float4(o0a, o0b, o1a, o1b));
    } else {
        __stcs(&out[i0], make_float2(o0a, o0b));
    }
}

extern "C" void kernel_launch(void* const* d_in, const int* in_sizes, int n_in,
                              void* d_out, int out_size) {
    const float* x = (const float*)d_in[0];
    const float2* ht = (const float2*)d_in[1];
    float2* out = (float2*)d_out;
    int n = in_sizes[0] / 3;

    densify_kernel<<<512, 256>>>(ht);

    int threads = 256;
    int pts_per_block = threads * 2;
    int blocks = (n + pts_per_block - 1) / pts_per_block;
    ngp_interp_kernel<<<blocks, threads>>>(x, out, n);
}